// round 9
// baseline (speedup 1.0000x reference)
#include <cuda_runtime.h>
#include <stdint.h>

// NaiveVisCache: per-ray cube-face select + morton3d index + cache gather + threshold.
// d_in[0] = norm_ray_origins (B,3) f32, d_in[1] = viewdirs (B,3) f32,
// d_in[2] = cache (128^3,6) int32. Output: B f32 (0.0/1.0).
//
// Semantics (verified rel_err=0.0): reference lowers v/inf_norm as
// v * fl_rn(1/inf_norm) -> __frcp_rn + __fmul_rn; where-chain falls back to
// face 0 when x*fl(1/x) rounds below 1.0.
//
// Perf strategy:
//  - streams: __ldcs / __stcs (L2 evict-first) — pure pass-through traffic
//  - gather:  ld.global.nc.L2::cache_hint with a createpolicy evict_last
//             policy (scalar ld + direct .L2::evict_last is illegal on
//             sm_100a; the cache-hint form is the legal equivalent) — pins
//             the 48MB table in L2 across graph replays
//  - 8 rays/thread -> 8 independent gathers in flight (MLP)

#define MIDPOINT 128

__device__ __forceinline__ unsigned expand_bits(unsigned v) {
    v = (v | (v << 16)) & 0x030000FFu;
    v = (v | (v << 8))  & 0x0300F00Fu;
    v = (v | (v << 4))  & 0x030C30C3u;
    v = (v | (v << 2))  & 0x09249249u;
    return v;
}

__device__ __forceinline__ uint64_t make_evict_last_policy() {
    uint64_t pol;
    asm("createpolicy.fractional.L2::evict_last.b64 %0, 1.0;" : "=l"(pol));
    return pol;
}

__device__ __forceinline__ int ldg_hint(const int* p, uint64_t pol) {
    int v;
    asm volatile("ld.global.nc.L2::cache_hint.s32 %0, [%1], %2;"
                 : "=r"(v) : "l"(p), "l"(pol));
    return v;
}

__global__ void __launch_bounds__(256)
vis_cache_kernel(const float4* __restrict__ org4,
                 const float4* __restrict__ dir4,
                 const int*    __restrict__ cache,
                 float4*       __restrict__ out4,
                 int n_oct)  // n_rays / 8
{
    int t = blockIdx.x * blockDim.x + threadIdx.x;
    if (t >= n_oct) return;

    uint64_t pol = make_evict_last_policy();

    // 8 rays = 24 floats = 6 float4 loads per array. Evict-first: pure stream.
    float4 o[6], v[6];
    #pragma unroll
    for (int k = 0; k < 6; k++) o[k] = __ldcs(&org4[6 * t + k]);
    #pragma unroll
    for (int k = 0; k < 6; k++) v[k] = __ldcs(&dir4[6 * t + k]);

    const float* of = reinterpret_cast<const float*>(o);
    const float* vf = reinterpret_cast<const float*>(v);

    // Phase 1: morton base indices (exact-integer path).
    unsigned base[8];
    #pragma unroll
    for (int j = 0; j < 8; j++) {
        float cx = fminf(fmaxf((of[3 * j + 0] * 0.5f + 0.5f) * 128.0f, 0.0f), 127.0f);
        float cy = fminf(fmaxf((of[3 * j + 1] * 0.5f + 0.5f) * 128.0f, 0.0f), 127.0f);
        float cz = fminf(fmaxf((of[3 * j + 2] * 0.5f + 0.5f) * 128.0f, 0.0f), 127.0f);

        unsigned idx = expand_bits((unsigned)(int)cx)
                     | (expand_bits((unsigned)(int)cy) << 1)
                     | (expand_bits((unsigned)(int)cz) << 2);
        base[j] = idx * 6u;
    }

    // Phase 2: face select (reciprocal-multiply, bit-matching the reference).
    unsigned addr[8];
    #pragma unroll
    for (int j = 0; j < 8; j++) {
        float a = vf[3 * j + 0];
        float b = vf[3 * j + 1];
        float c = vf[3 * j + 2];

        float n = fmaxf(fabsf(a), fmaxf(fabsf(b), fabsf(c)));
        float r  = __frcp_rn(n);
        float sa = __fmul_rn(a, r);
        float sb = __fmul_rn(b, r);
        float sc = __fmul_rn(c, r);

        int face = 0;
        if (sa >=  1.0f) face = 0;
        if (sa <= -1.0f) face = 1;
        if (sb >=  1.0f) face = 2;
        if (sb <= -1.0f) face = 3;
        if (sc >=  1.0f) face = 4;
        if (sc <= -1.0f) face = 5;

        addr[j] = base[j] + (unsigned)face;
    }

    // Phase 3: 8 independent gathers in flight; table lines tagged evict-last.
    int val[8];
    #pragma unroll
    for (int j = 0; j < 8; j++) val[j] = ldg_hint(&cache[addr[j]], pol);

    float4 r0 = make_float4(val[0] > MIDPOINT ? 1.0f : 0.0f,
                            val[1] > MIDPOINT ? 1.0f : 0.0f,
                            val[2] > MIDPOINT ? 1.0f : 0.0f,
                            val[3] > MIDPOINT ? 1.0f : 0.0f);
    float4 r1 = make_float4(val[4] > MIDPOINT ? 1.0f : 0.0f,
                            val[5] > MIDPOINT ? 1.0f : 0.0f,
                            val[6] > MIDPOINT ? 1.0f : 0.0f,
                            val[7] > MIDPOINT ? 1.0f : 0.0f);

    __stcs(&out4[2 * t + 0], r0);
    __stcs(&out4[2 * t + 1], r1);
}

extern "C" void kernel_launch(void* const* d_in, const int* in_sizes, int n_in,
                              void* d_out, int out_size)
{
    const float4* org4  = (const float4*)d_in[0];
    const float4* dir4  = (const float4*)d_in[1];
    const int*    cache = (const int*)d_in[2];
    float4*       out4  = (float4*)d_out;

    int n_rays = in_sizes[0] / 3;   // 4194304
    int n_oct  = n_rays / 8;        // 524288

    int threads = 256;
    int blocks  = (n_oct + threads - 1) / threads;
    vis_cache_kernel<<<blocks, threads>>>(org4, dir4, cache, out4, n_oct);
}